// round 4
// baseline (speedup 1.0000x reference)
#include <cuda_runtime.h>
#include <cuda_bf16.h>
#include <cstdint>

// ---------------- problem constants ----------------
#define BS   32
#define C    64
#define H    96
#define W    96
#define HW   (H*W)            // 9216
#define CHW  (C*HW)           // 589824
#define TT   64               // num types
#define HID  128              // 2c
#define EPS  1e-5f

// conv tiling
#define TILE_X 32
#define TILE_Y 8
#define TROWS  (TILE_Y+2)     // 10
#define TCOLS  35             // 32+2 halo, padded to 35 for conflict-free LDS
#define TILE_ELEMS (C*TROWS*TCOLS)   // 22400
#define WK_ELEMS   (C*C)             // 4096
#define WSUM_ELEMS (8*16)            // 128
#define CONV_SMEM_FLOATS (TILE_ELEMS + WSUM_ELEMS)
#define CONV_SMEM_BYTES  (CONV_SMEM_FLOATS*4)   // ~90KB -> 2 CTA/SM

#define NTILES_X (W/TILE_X)   // 3
#define NTILES_Y (H/TILE_Y)   // 12
#define NTILES   (NTILES_X*NTILES_Y) // 36

// tail smem: w1s(8192)+w2s(8192)+feat(2048)+hidden(4096)+logit(2048)
//            +refnew(4096)+refx(2048)+misc(160)
#define TAIL_SMEM_FLOATS (8192+8192+2048+4096+2048+4096+2048+160)
#define TAIL_SMEM_BYTES  (TAIL_SMEM_FLOATS*4)

// ---------------- device scratch (static: no runtime allocs allowed) ----
__device__ float g_f1[BS*CHW];                 // intermediate feature map (~75.5MB)
__device__ float g_wf1[9*C*C];                 // folded conv1 weights [k][ic][oc]
__device__ float g_wf2[9*C*C];
__device__ float g_bias1[C];
__device__ float g_bias2[C];
__device__ float g_part[BS*NTILES*C];          // pooled partial sums per tile

// ---------------- prep: fold BN into weights, layout [k][ic][oc] --------
__global__ void prep_kernel(const float* __restrict__ w1, const float* __restrict__ g1,
                            const float* __restrict__ b1, const float* __restrict__ m1,
                            const float* __restrict__ v1,
                            const float* __restrict__ w2, const float* __restrict__ g2,
                            const float* __restrict__ b2, const float* __restrict__ m2,
                            const float* __restrict__ v2) {
    int idx = blockIdx.x*256 + threadIdx.x;
    if (idx < 9*C*C) {
        int oc = idx & 63;
        int ic = (idx >> 6) & 63;
        int k  = idx >> 12;
        float s1 = g1[oc] * rsqrtf(v1[oc] + EPS);
        float s2 = g2[oc] * rsqrtf(v2[oc] + EPS);
        // source layout: w[oc][ic][ky][kx]
        g_wf1[idx] = w1[(oc*C + ic)*9 + k] * s1;
        g_wf2[idx] = w2[(oc*C + ic)*9 + k] * s2;
    }
    if (idx < C) {
        g_bias1[idx] = b1[idx] - m1[idx]*g1[idx]*rsqrtf(v1[idx] + EPS);
        g_bias2[idx] = b2[idx] - m2[idx]*g2[idx]*rsqrtf(v2[idx] + EPS);
    }
}

// ---------------- direct conv, 16 oc x 4 px per thread, f32x2 accs ------
// Weights streamed from L2 via warp-uniform LDG.128 (no smem staging, 1 sync).
// STORE=1: read param input, write relu result to g_f1
// STORE=0: read g_f1, reduce relu result spatially into g_part
template<int STORE>
__launch_bounds__(256, 2)
__global__ void conv_kernel(const float* __restrict__ xin) {
    extern __shared__ float smem[];
    float* tile = smem;                       // [C][TROWS][TCOLS]
    float* wsum = smem + TILE_ELEMS;          // [8 warps][16]

    const int tid = threadIdx.x;
    const int oc0 = (tid >> 6) << 4;          // 16 oc per thread
    const int p = tid & 63;
    const int row = p >> 3;                   // 0..7
    const int colbase = (p & 7) << 2;         // 0,4,...,28  (4 px per thread)

    const int x0 = blockIdx.x * TILE_X, y0 = blockIdx.y * TILE_Y;
    const int b  = blockIdx.z;

    const float* in   = STORE ? xin : g_f1;
    const float* wf   = STORE ? g_wf1 : g_wf2;
    const float* bias = STORE ? g_bias1 : g_bias2;
    const float* inb  = in + (size_t)b * CHW;

    // load input tile with halo (zero pad at borders)
    for (int idx = tid; idx < TILE_ELEMS; idx += 256) {
        int ch  = idx / (TROWS*TCOLS);
        int rem = idx - ch*(TROWS*TCOLS);
        int r   = rem / TCOLS;
        int col = rem - r*TCOLS;
        int gy = y0 + r - 1, gx = x0 + col - 1;
        float v = 0.f;
        if (gy >= 0 && gy < H && gx >= 0 && gx < W && col < 34)
            v = inb[ch*HW + gy*W + gx];
        tile[idx] = v;
    }
    __syncthreads();   // the ONLY barrier before the epilogue

    unsigned long long acc[8][4];   // acc[j][q]: oc pair (oc0+2j, oc0+2j+1), pixel q
#pragma unroll
    for (int j = 0; j < 8; j++)
#pragma unroll
        for (int q = 0; q < 4; q++) acc[j][q] = 0ull;

    const float* wth = wf + oc0;    // per-thread (warp-uniform) weight base

#pragma unroll 2
    for (int ic = 0; ic < C; ic++) {
        const float* xcol = tile + ic*(TROWS*TCOLS) + row*TCOLS + colbase;
        const float4* wic = (const float4*)(wth + ic*C);
#pragma unroll
        for (int k = 0; k < 9; k++) {
            const int ky = k/3, kx = k - 3*(k/3);
            // 4 pixel activations, duplicated into f32x2
            unsigned long long xx[4];
#pragma unroll
            for (int q = 0; q < 4; q++) {
                float xv = xcol[ky*TCOLS + kx + q];
                asm("mov.b64 %0, {%1, %1};" : "=l"(xx[q]) : "f"(xv));
            }
            // 16 weights for this (k, ic), warp-uniform LDG.128 from L2
            const float4* wq = wic + k*(WK_ELEMS/4);
            float4 wa = __ldg(wq+0), wb = __ldg(wq+1);
            float4 wc = __ldg(wq+2), wd = __ldg(wq+3);
            unsigned long long wv[8];
            asm("mov.b64 %0, {%1, %2};" : "=l"(wv[0]) : "f"(wa.x), "f"(wa.y));
            asm("mov.b64 %0, {%1, %2};" : "=l"(wv[1]) : "f"(wa.z), "f"(wa.w));
            asm("mov.b64 %0, {%1, %2};" : "=l"(wv[2]) : "f"(wb.x), "f"(wb.y));
            asm("mov.b64 %0, {%1, %2};" : "=l"(wv[3]) : "f"(wb.z), "f"(wb.w));
            asm("mov.b64 %0, {%1, %2};" : "=l"(wv[4]) : "f"(wc.x), "f"(wc.y));
            asm("mov.b64 %0, {%1, %2};" : "=l"(wv[5]) : "f"(wc.z), "f"(wc.w));
            asm("mov.b64 %0, {%1, %2};" : "=l"(wv[6]) : "f"(wd.x), "f"(wd.y));
            asm("mov.b64 %0, {%1, %2};" : "=l"(wv[7]) : "f"(wd.z), "f"(wd.w));
#pragma unroll
            for (int j = 0; j < 8; j++)
#pragma unroll
                for (int q = 0; q < 4; q++)
                    asm("fma.rn.f32x2 %0, %1, %2, %0;"
                        : "+l"(acc[j][q]) : "l"(wv[j]), "l"(xx[q]));
        }
    }

    const int gy = y0 + row;
    const int gx = x0 + colbase;
    if (STORE) {
        float* op = g_f1 + (size_t)b*CHW + gy*W + gx;
#pragma unroll
        for (int j = 0; j < 8; j++) {
            float lo[4], hi[4];
#pragma unroll
            for (int q = 0; q < 4; q++)
                asm("mov.b64 {%0, %1}, %2;" : "=f"(lo[q]), "=f"(hi[q]) : "l"(acc[j][q]));
            float blo = bias[oc0 + 2*j], bhi = bias[oc0 + 2*j + 1];
            float4 vlo, vhi;
            vlo.x = fmaxf(lo[0]+blo, 0.f); vlo.y = fmaxf(lo[1]+blo, 0.f);
            vlo.z = fmaxf(lo[2]+blo, 0.f); vlo.w = fmaxf(lo[3]+blo, 0.f);
            vhi.x = fmaxf(hi[0]+bhi, 0.f); vhi.y = fmaxf(hi[1]+bhi, 0.f);
            vhi.z = fmaxf(hi[2]+bhi, 0.f); vhi.w = fmaxf(hi[3]+bhi, 0.f);
            *(float4*)(op + (size_t)(oc0 + 2*j    )*HW) = vlo;
            *(float4*)(op + (size_t)(oc0 + 2*j + 1)*HW) = vhi;
        }
    } else {
        const int warp = tid >> 5;
        const int lane = tid & 31;
#pragma unroll
        for (int j = 0; j < 8; j++) {
            float lo[4], hi[4];
#pragma unroll
            for (int q = 0; q < 4; q++)
                asm("mov.b64 {%0, %1}, %2;" : "=f"(lo[q]), "=f"(hi[q]) : "l"(acc[j][q]));
            float blo = bias[oc0 + 2*j], bhi = bias[oc0 + 2*j + 1];
            float slo = fmaxf(lo[0]+blo,0.f) + fmaxf(lo[1]+blo,0.f)
                      + fmaxf(lo[2]+blo,0.f) + fmaxf(lo[3]+blo,0.f);
            float shi = fmaxf(hi[0]+bhi,0.f) + fmaxf(hi[1]+bhi,0.f)
                      + fmaxf(hi[2]+bhi,0.f) + fmaxf(hi[3]+bhi,0.f);
#pragma unroll
            for (int s = 16; s; s >>= 1) {
                slo += __shfl_xor_sync(0xffffffffu, slo, s);
                shi += __shfl_xor_sync(0xffffffffu, shi, s);
            }
            if (lane == 0) {
                wsum[warp*16 + 2*j    ] = slo;
                wsum[warp*16 + 2*j + 1] = shi;
            }
        }
        __syncthreads();
        if (tid < C) {
            int g = tid >> 4, r = tid & 15;
            float s = wsum[(2*g)*16 + r] + wsum[(2*g+1)*16 + r];
            int tileIdx = blockIdx.y * NTILES_X + blockIdx.x;
            g_part[((size_t)b*NTILES + tileIdx)*C + tid] = s;
        }
    }
}

// ---------------- tail: pool, MLP, softmax, loss, EMA scatter, output ---
__launch_bounds__(1024)
__global__ void tail_kernel(const float* __restrict__ ref_x, const int* __restrict__ ref_types,
                            const float* __restrict__ w1, const float* __restrict__ b1,
                            const float* __restrict__ w2, const float* __restrict__ b2,
                            const float* __restrict__ ref_proj, float* __restrict__ dout) {
    extern __shared__ float sm[];
    float* w1s    = sm;              // [64][128]
    float* w2s    = w1s + 8192;      // [128][64]
    float* feat   = w2s + 8192;      // [32][64]
    float* hidden = feat + 2048;     // [32][128]
    float* logit  = hidden + 4096;   // [32][64] -> becomes type_weights
    float* refnew = logit + 2048;    // [64][64]
    float* refx   = refnew + 4096;   // [32][64]
    float* lossv  = refx + 2048;     // [32]
    float* coeff  = lossv + 32;      // [32]
    float* decay  = coeff + 32;      // [64]
    int*   st     = (int*)(decay + 64); // [32]

    const int tid = threadIdx.x;
    const int NTH = 1024;
    if (tid < BS) st[tid] = ref_types[tid];

    // stage weights + ref_x, finish pooling (all independent)
    for (int i = tid; i < 8192; i += NTH) { w1s[i] = w1[i]; w2s[i] = w2[i]; }
    for (int i = tid; i < BS*C; i += NTH) refx[i] = ref_x[i];
    for (int idx = tid; idx < BS*C; idx += NTH) {
        int bb = idx >> 6, c = idx & 63;
        float s = 0.f;
#pragma unroll 6
        for (int t = 0; t < NTILES; t++) s += g_part[((size_t)bb*NTILES + t)*C + c];
        feat[idx] = s * (1.f/(float)HW);
    }
    __syncthreads();

    // hidden = relu(feat @ w1 + b1)    w1: [64][128]  (4 outputs/thread)
    for (int idx = tid; idx < BS*HID; idx += NTH) {
        int bb = idx >> 7, j = idx & 127;
        float s = b1[j];
        const float* fr = feat + bb*C;
#pragma unroll 16
        for (int i = 0; i < C; i++) s += fr[i] * w1s[i*HID + j];
        hidden[idx] = fmaxf(s, 0.f);
    }
    __syncthreads();

    // logits = hidden @ w2 + b2       w2: [128][64]  (2 outputs/thread)
    for (int idx = tid; idx < BS*TT; idx += NTH) {
        int bb = idx >> 6, t = idx & 63;
        float s = b2[t];
        const float* hr = hidden + bb*HID;
#pragma unroll 16
        for (int j = 0; j < HID; j++) s += hr[j] * w2s[j*TT + t];
        logit[idx] = s;
    }
    __syncthreads();

    // warp-per-row softmax (32 warps = 32 rows), 2 logits per lane
    {
        const int wp = tid >> 5, ln = tid & 31;
        float* lr = logit + wp*TT;
        float a = lr[ln], c2 = lr[ln + 32];
        float tgt = lr[st[wp]];
        float mx = fmaxf(a, c2);
#pragma unroll
        for (int s = 16; s; s >>= 1) mx = fmaxf(mx, __shfl_xor_sync(0xffffffffu, mx, s));
        float ea = expf(a - mx), eb = expf(c2 - mx);
        float sum = ea + eb;
#pragma unroll
        for (int s = 16; s; s >>= 1) sum += __shfl_xor_sync(0xffffffffu, sum, s);
        if (ln == 0) lossv[wp] = mx + logf(sum) - tgt;
        float inv = 1.f / sum;
        __syncwarp();
        lr[ln]      = ea * inv;
        lr[ln + 32] = eb * inv;
    }
    // EMA coefficients
    if (tid < TT) {
        int cnt = 0;
        for (int i = 0; i < BS; i++) cnt += (st[i] == tid);
        float r = 1.f;
        for (int q = 0; q < cnt; q++) r *= 0.99f;
        decay[tid] = r;
    }
    if (tid >= 64 && tid < 96) {
        int i = tid - 64;
        int after = 0;
        for (int j = i + 1; j < BS; j++) after += (st[j] == st[i]);
        float r = 0.01f;
        for (int q = 0; q < after; q++) r *= 0.99f;
        coeff[i] = r;
    }
    __syncthreads();

    // ref_new[t][c] = decay[t]*ref_proj + sum_{i: type_i==t} coeff[i]*ref_x[i]
    for (int idx = tid; idx < TT*C; idx += NTH) {
        int t = idx >> 6, c = idx & 63;
        float v = decay[t] * ref_proj[idx];
#pragma unroll 8
        for (int i = 0; i < BS; i++)
            if (st[i] == t) v += coeff[i] * refx[i*C + c];
        refnew[idx] = v;
        dout[2049 + idx] = v;   // output 3: ref_new [64,64]
    }
    __syncthreads();

    // out[b][c] = ref_x + tw[b] @ ref_new   (2 outputs/thread)
    for (int idx = tid; idx < BS*C; idx += NTH) {
        int bb = idx >> 6, c = idx & 63;
        float s = refx[idx];
        const float* twr = logit + bb*TT;
#pragma unroll 16
        for (int t = 0; t < TT; t++) s += twr[t] * refnew[t*C + c];
        dout[idx] = s;          // output 1: out [32,64,1,1]
    }
    if (tid == 0) {
        float s = 0.f;
        for (int i = 0; i < BS; i++) s += lossv[i];
        dout[2048] = s * (1.f/(float)BS);   // output 2: loss
    }
}

// ---------------- launch ----------------
extern "C" void kernel_launch(void* const* d_in, const int* in_sizes, int n_in,
                              void* d_out, int out_size) {
    const float* x        = (const float*)d_in[0];
    const float* ref_x    = (const float*)d_in[1];
    const int*   ref_types= (const int*)  d_in[2];
    const float* conv1_w  = (const float*)d_in[3];
    const float* bn1_g    = (const float*)d_in[4];
    const float* bn1_b    = (const float*)d_in[5];
    const float* bn1_m    = (const float*)d_in[6];
    const float* bn1_v    = (const float*)d_in[7];
    const float* conv2_w  = (const float*)d_in[8];
    const float* bn2_g    = (const float*)d_in[9];
    const float* bn2_b    = (const float*)d_in[10];
    const float* bn2_m    = (const float*)d_in[11];
    const float* bn2_v    = (const float*)d_in[12];
    const float* mlp_w1   = (const float*)d_in[13];
    const float* mlp_b1   = (const float*)d_in[14];
    const float* mlp_w2   = (const float*)d_in[15];
    const float* mlp_b2   = (const float*)d_in[16];
    const float* ref_proj = (const float*)d_in[17];
    float* out = (float*)d_out;

    cudaFuncSetAttribute(conv_kernel<1>, cudaFuncAttributeMaxDynamicSharedMemorySize, CONV_SMEM_BYTES);
    cudaFuncSetAttribute(conv_kernel<0>, cudaFuncAttributeMaxDynamicSharedMemorySize, CONV_SMEM_BYTES);
    cudaFuncSetAttribute(tail_kernel,    cudaFuncAttributeMaxDynamicSharedMemorySize, TAIL_SMEM_BYTES);

    prep_kernel<<<144, 256>>>(conv1_w, bn1_g, bn1_b, bn1_m, bn1_v,
                              conv2_w, bn2_g, bn2_b, bn2_m, bn2_v);

    dim3 cgrid(NTILES_X, NTILES_Y, BS);
    conv_kernel<1><<<cgrid, 256, CONV_SMEM_BYTES>>>(x);
    conv_kernel<0><<<cgrid, 256, CONV_SMEM_BYTES>>>(x);

    tail_kernel<<<1, 1024, TAIL_SMEM_BYTES>>>(ref_x, ref_types, mlp_w1, mlp_b1,
                                              mlp_w2, mlp_b2, ref_proj, out);
}

// round 6
// speedup vs baseline: 2.2228x; 2.2228x over previous
#include <cuda_runtime.h>
#include <cuda_bf16.h>
#include <cstdint>

// ---------------- problem constants ----------------
#define BS   32
#define C    64
#define H    96
#define W    96
#define HW   (H*W)
#define CHW  ((size_t)C*HW)
#define TT   64
#define HID  128
#define EPS  1e-5f

// conv tiling: CTA = 4 rows x 32 cols = 128 px (M), 64 oc (N), K = 9*64
#define NTX 3
#define NTY 24
#define NT  (NTX*NTY)        // 72 tiles/image

// halo tile: 6 rows x 34 cols = 204 pixel-rows, each 64 bf16 = 128B
#define TPX 204
#define OFF_TH 0
#define OFF_TL 26624
#define OFF_B0 53248
#define OFF_B1 69632
#define CONV_SMEM 86016      // 2 CTAs/SM (172KB < 228KB)

#define TAIL_SMEM_FLOATS (8192+8192+2048+4096+2048+4096+2048+160)
#define TAIL_SMEM_BYTES  (TAIL_SMEM_FLOATS*4)

// ---------------- device scratch ----------------
__device__ uint32_t g_x [BS*CHW];     // x, pixel-major packed (bf16hi<<16)|bf16lo
__device__ uint32_t g_f1[BS*CHW];     // conv1 out, same format
__device__ uint32_t g_wbm1[9*4096];   // weights: per slice 16KB = hi 8KB + lo 8KB, ldsm-swizzled
__device__ uint32_t g_wbm2[9*4096];
__device__ float    g_bias1[C];
__device__ float    g_bias2[C];
__device__ float    g_part[BS*NT*C];

// ---------------- helpers ----------------
static __device__ __forceinline__ uint32_t smem_u32(const void* p) {
    uint32_t a;
    asm("{ .reg .u64 t; cvta.to.shared.u64 t, %1; cvt.u32.u64 %0, t; }" : "=r"(a) : "l"(p));
    return a;
}
static __device__ __forceinline__ uint32_t split_pack(float v) {
    __nv_bfloat16 h = __float2bfloat16(v);
    float res = v - __bfloat162float(h);
    __nv_bfloat16 l = __float2bfloat16(res);
    return ((uint32_t)__bfloat16_as_ushort(h) << 16) | (uint32_t)__bfloat16_as_ushort(l);
}
static __device__ __forceinline__ void ldsm4(uint32_t* r, uint32_t a) {
    asm volatile("ldmatrix.sync.aligned.m8n8.x4.shared.b16 {%0,%1,%2,%3}, [%4];"
        : "=r"(r[0]), "=r"(r[1]), "=r"(r[2]), "=r"(r[3]) : "r"(a));
}
static __device__ __forceinline__ void mma16816(float* c, const uint32_t* a, const uint32_t* b) {
    asm volatile("mma.sync.aligned.m16n8k16.row.col.f32.bf16.bf16.f32 "
        "{%0,%1,%2,%3}, {%4,%5,%6,%7}, {%8,%9}, {%0,%1,%2,%3};"
        : "+f"(c[0]), "+f"(c[1]), "+f"(c[2]), "+f"(c[3])
        : "r"(a[0]), "r"(a[1]), "r"(a[2]), "r"(a[3]), "r"(b[0]), "r"(b[1]));
}
static __device__ __forceinline__ void cp16(uint32_t dst, const void* src) {
    asm volatile("cp.async.cg.shared.global [%0], [%1], 16;" :: "r"(dst), "l"(src));
}
static __device__ __forceinline__ void cp_commit() {
    asm volatile("cp.async.commit_group;" ::: "memory");
}
static __device__ __forceinline__ void cp_wait0() {
    asm volatile("cp.async.wait_group 0;" ::: "memory");
}

// ---------------- transpose x: [ic][py][px] fp32 -> [px][ic] packed ----
__global__ void xpose_kernel(const float* __restrict__ x) {
    __shared__ float st[64*65];
    const int tid = threadIdx.x;
    const int b = blockIdx.y;
    const int p0 = blockIdx.x * 64;
    const float* xb = x + (size_t)b * CHW;
    for (int i = tid; i < 64*64; i += 256) {
        int ic = i >> 6, p = i & 63;
        st[p*65 + ic] = xb[(size_t)ic*HW + p0 + p];
    }
    __syncthreads();
    for (int i = tid; i < 64*32; i += 256) {
        int p = i >> 5, pr = i & 31;
        uint2 v;
        v.x = split_pack(st[p*65 + 2*pr]);
        v.y = split_pack(st[p*65 + 2*pr + 1]);
        *(uint2*)(g_x + ((size_t)(b*HW + p0 + p) << 6) + 2*pr) = v;
    }
}

// ---------------- prep: fold BN, split hi/lo, ldsm-swizzle weights -----
__global__ void prep_kernel(const float* __restrict__ w1, const float* __restrict__ g1,
                            const float* __restrict__ b1, const float* __restrict__ m1,
                            const float* __restrict__ v1,
                            const float* __restrict__ w2, const float* __restrict__ g2,
                            const float* __restrict__ b2, const float* __restrict__ m2,
                            const float* __restrict__ v2) {
    int idx = blockIdx.x*256 + threadIdx.x;
    if (idx < 2*9*4096) {
        int cv = idx / 36864;
        int r  = idx - cv*36864;
        int s  = r >> 12;
        int q  = r & 4095;
        int oc = q >> 6;
        int ic = q & 63;
        const float* w = cv ? w2 : w1;
        const float* g = cv ? g2 : g1;
        const float* v = cv ? v2 : v1;
        float f = w[(oc*C + ic)*9 + s] * (g[oc] * rsqrtf(v[oc] + EPS));
        __nv_bfloat16 h = __float2bfloat16(f);
        float res = f - __bfloat162float(h);
        __nv_bfloat16 l = __float2bfloat16(res);
        // row = oc (128B of 64 bf16), swizzle elem: ic ^ ((oc&7)<<3)
        uint32_t e = (uint32_t)oc*64 + ((uint32_t)ic ^ (((uint32_t)oc & 7u) << 3));
        __nv_bfloat16* dst = (__nv_bfloat16*)(cv ? g_wbm2 : g_wbm1) + (size_t)s*8192;
        dst[e]        = h;
        dst[4096 + e] = l;
    }
    if (idx < C) {
        g_bias1[idx] = b1[idx] - m1[idx]*g1[idx]*rsqrtf(v1[idx] + EPS);
        g_bias2[idx] = b2[idx] - m2[idx]*g2[idx]*rsqrtf(v2[idx] + EPS);
    }
}

// ---------------- HMMA conv: 3xBF16-compensated implicit GEMM ----------
// STORE=1: reads g_x, writes g_f1 (pixel-major packed)
// STORE=0: reads g_f1, writes pooled partials -> g_part
template<int STORE>
__launch_bounds__(256, 2)
__global__ void conv_mma(int dummy) {
    extern __shared__ uint8_t sm[];
    const uint32_t sb = smem_u32(sm);

    const int tid  = threadIdx.x;
    const int lane = tid & 31;
    const int wrp  = tid >> 5;
    const int x0 = blockIdx.x * 32, y0 = blockIdx.y * 4;
    const int b  = blockIdx.z;

    const uint32_t* gin = STORE ? g_x : g_f1;
    const uint32_t* gwb = STORE ? g_wbm1 : g_wbm2;
    const float*   bias = STORE ? g_bias1 : g_bias2;

    // prefetch B slice 0
    {
        uint32_t dst = sb + OFF_B0;
        #pragma unroll
        for (int i = 0; i < 4; i++)
            cp16(dst + (tid + i*256)*16, gwb + (size_t)(tid + i*256)*4);
        cp_commit();
    }

    // fill halo tile (pixel-major packed -> two bf16 planes, swizzled)
    const uint32_t* inb = gin + (size_t)b * CHW;
    for (int i = tid; i < TPX*32; i += 256) {
        int pxl = i >> 5, pr = i & 31;
        int rr = pxl / 34, cc = pxl - rr*34;
        int py = y0 + rr - 1, px = x0 + cc - 1;
        uint32_t hp = 0, lp = 0;
        if (py >= 0 && py < H && px >= 0 && px < W) {
            uint2 v = *(const uint2*)(inb + ((size_t)(py*W + px) << 6) + 2*pr);
            hp = __byte_perm(v.x, v.y, 0x7632);
            lp = __byte_perm(v.x, v.y, 0x5410);
        }
        uint32_t boff = (uint32_t)pxl*128 + (((uint32_t)pr*4) ^ (((uint32_t)pxl & 7u) << 4));
        *(uint32_t*)(sm + OFF_TH + boff) = hp;
        *(uint32_t*)(sm + OFF_TL + boff) = lp;
    }

    // per-lane ldsm address components
    const int g  = lane >> 3, lr = lane & 7;
    const int mb = (wrp & 3) * 32;
    const int nb = (wrp >> 2) * 32;
    const uint32_t kaddA = (g >= 2) ? 16u : 0u;
    const uint32_t kaddB = (uint32_t)(g & 1) << 4;
    int pA[2];
    uint32_t bRow[2], bSwz[2];
    #pragma unroll
    for (int f = 0; f < 2; f++) {
        int p = mb + f*16 + ((g & 1) << 3) + lr;
        pA[f] = (p >> 5)*34 + (p & 31);
        int oc = nb + f*16 + ((g >= 2) ? 8 : 0) + lr;
        bRow[f] = (uint32_t)oc * 128;
        bSwz[f] = ((uint32_t)oc & 7u) << 4;
    }

    float acc[2][4][4];
    #pragma unroll
    for (int m = 0; m < 2; m++)
        #pragma unroll
        for (int n = 0; n < 4; n++)
            #pragma unroll
            for (int q = 0; q < 4; q++) acc[m][n][q] = 0.f;

    for (int s = 0; s < 9; s++) {
        cp_wait0();
        __syncthreads();
        if (s < 8) {
            uint32_t dst = sb + (((s+1) & 1) ? OFF_B1 : OFF_B0);
            const uint32_t* src = gwb + (size_t)(s+1)*4096;
            #pragma unroll
            for (int i = 0; i < 4; i++)
                cp16(dst + (tid + i*256)*16, src + (size_t)(tid + i*256)*4);
            cp_commit();
        }
        const int ky = s / 3, kx = s - 3*(s/3);
        const int soff = ky*34 + kx;
        const uint32_t bbuf = sb + ((s & 1) ? OFF_B1 : OFF_B0);

        #pragma unroll
        for (int kc = 0; kc < 4; kc++) {
            uint32_t AH[2][4], AL[2][4], BH[4][2], BL[4][2];
            #pragma unroll
            for (int f = 0; f < 2; f++) {
                uint32_t pxl = (uint32_t)(pA[f] + soff);
                uint32_t aoff = pxl*128 + (((uint32_t)kc*32 + kaddA) ^ ((pxl & 7u) << 4));
                ldsm4(AH[f], sb + OFF_TH + aoff);
                ldsm4(AL[f], sb + OFF_TL + aoff);
            }
            #pragma unroll
            for (int f = 0; f < 2; f++) {
                uint32_t koff = ((uint32_t)kc*32 + kaddB);
                uint32_t r[4];
                ldsm4(r, bbuf + bRow[f] + (koff ^ bSwz[f]));
                BH[f*2][0] = r[0]; BH[f*2][1] = r[1];
                BH[f*2+1][0] = r[2]; BH[f*2+1][1] = r[3];
                ldsm4(r, bbuf + 8192 + bRow[f] + (koff ^ bSwz[f]));
                BL[f*2][0] = r[0]; BL[f*2][1] = r[1];
                BL[f*2+1][0] = r[2]; BL[f*2+1][1] = r[3];
            }
            #pragma unroll
            for (int m = 0; m < 2; m++)
                #pragma unroll
                for (int n = 0; n < 4; n++) {
                    mma16816(acc[m][n], AH[m], BH[n]);
                    mma16816(acc[m][n], AH[m], BL[n]);
                    mma16816(acc[m][n], AL[m], BH[n]);
                }
        }
    }

    // ---------------- epilogue ----------------
    if (STORE) {
        #pragma unroll
        for (int m = 0; m < 2; m++) {
            #pragma unroll
            for (int n = 0; n < 4; n++) {
                int oc = nb + n*8 + (lane & 3)*2;
                float b0 = bias[oc], b1v = bias[oc+1];
                #pragma unroll
                for (int hh = 0; hh < 2; hh++) {
                    int p = mb + m*16 + (lane >> 2) + hh*8;
                    int py = y0 + (p >> 5), px = x0 + (p & 31);
                    uint2 v;
                    v.x = split_pack(fmaxf(acc[m][n][hh*2]   + b0,  0.f));
                    v.y = split_pack(fmaxf(acc[m][n][hh*2+1] + b1v, 0.f));
                    *(uint2*)(g_f1 + ((size_t)b*CHW) + ((size_t)(py*W + px) << 6) + oc) = v;
                }
            }
        }
    } else {
        float cs[4][2];
        #pragma unroll
        for (int n = 0; n < 4; n++) {
            int oc = nb + n*8 + (lane & 3)*2;
            float b0 = bias[oc], b1v = bias[oc+1];
            float s0 = 0.f, s1 = 0.f;
            #pragma unroll
            for (int m = 0; m < 2; m++) {
                s0 += fmaxf(acc[m][n][0] + b0, 0.f) + fmaxf(acc[m][n][2] + b0, 0.f);
                s1 += fmaxf(acc[m][n][1] + b1v, 0.f) + fmaxf(acc[m][n][3] + b1v, 0.f);
            }
            #pragma unroll
            for (int d = 4; d < 32; d <<= 1) {
                s0 += __shfl_xor_sync(0xffffffffu, s0, d);
                s1 += __shfl_xor_sync(0xffffffffu, s1, d);
            }
            cs[n][0] = s0; cs[n][1] = s1;
        }
        __syncthreads();                       // tile reads done -> reuse as pool
        float* pool = (float*)(sm + OFF_TH);   // [4 mrow][64 oc]
        if (lane < 4) {
            #pragma unroll
            for (int n = 0; n < 4; n++) {
                int oc = nb + n*8 + lane*2;
                pool[(wrp & 3)*64 + oc]     = cs[n][0];
                pool[(wrp & 3)*64 + oc + 1] = cs[n][1];
            }
        }
        __syncthreads();
        if (tid < C) {
            float s = pool[tid] + pool[64 + tid] + pool[128 + tid] + pool[192 + tid];
            int tileIdx = blockIdx.y * NTX + blockIdx.x;
            g_part[((size_t)b*NT + tileIdx)*C + tid] = s;
        }
    }
}

// ---------------- tail: pool, MLP, softmax, loss, EMA, outputs ----------
__launch_bounds__(1024)
__global__ void tail_kernel(const float* __restrict__ ref_x, const int* __restrict__ ref_types,
                            const float* __restrict__ w1, const float* __restrict__ b1,
                            const float* __restrict__ w2, const float* __restrict__ b2,
                            const float* __restrict__ ref_proj, float* __restrict__ dout) {
    extern __shared__ float smf[];
    float* w1s    = smf;
    float* w2s    = w1s + 8192;
    float* feat   = w2s + 8192;
    float* hidden = feat + 2048;
    float* logit  = hidden + 4096;
    float* refnew = logit + 2048;
    float* refx   = refnew + 4096;
    float* lossv  = refx + 2048;
    float* coeff  = lossv + 32;
    float* decay  = coeff + 32;
    int*   st     = (int*)(decay + 64);

    const int tid = threadIdx.x;
    const int NTH = 1024;
    if (tid < BS) st[tid] = ref_types[tid];

    for (int i = tid; i < 8192; i += NTH) { w1s[i] = w1[i]; w2s[i] = w2[i]; }
    for (int i = tid; i < BS*C; i += NTH) refx[i] = ref_x[i];
    for (int idx = tid; idx < BS*C; idx += NTH) {
        int bb = idx >> 6, c = idx & 63;
        float s = 0.f;
        #pragma unroll 8
        for (int t = 0; t < NT; t++) s += g_part[((size_t)bb*NT + t)*C + c];
        feat[idx] = s * (1.f/(float)HW);
    }
    __syncthreads();

    for (int idx = tid; idx < BS*HID; idx += NTH) {
        int bb = idx >> 7, j = idx & 127;
        float s = b1[j];
        const float* fr = feat + bb*C;
        #pragma unroll 16
        for (int i = 0; i < C; i++) s += fr[i] * w1s[i*HID + j];
        hidden[idx] = fmaxf(s, 0.f);
    }
    __syncthreads();

    for (int idx = tid; idx < BS*TT; idx += NTH) {
        int bb = idx >> 6, t = idx & 63;
        float s = b2[t];
        const float* hr = hidden + bb*HID;
        #pragma unroll 16
        for (int j = 0; j < HID; j++) s += hr[j] * w2s[j*TT + t];
        logit[idx] = s;
    }
    __syncthreads();

    {
        const int wp = tid >> 5, ln = tid & 31;
        float* lr = logit + wp*TT;
        float a = lr[ln], c2 = lr[ln + 32];
        float tgt = lr[st[wp]];
        float mx = fmaxf(a, c2);
        #pragma unroll
        for (int s = 16; s; s >>= 1) mx = fmaxf(mx, __shfl_xor_sync(0xffffffffu, mx, s));
        float ea = expf(a - mx), eb = expf(c2 - mx);
        float sum = ea + eb;
        #pragma unroll
        for (int s = 16; s; s >>= 1) sum += __shfl_xor_sync(0xffffffffu, sum, s);
        if (ln == 0) lossv[wp] = mx + logf(sum) - tgt;
        float inv = 1.f / sum;
        __syncwarp();
        lr[ln]      = ea * inv;
        lr[ln + 32] = eb * inv;
    }
    if (tid < TT) {
        int cnt = 0;
        for (int i = 0; i < BS; i++) cnt += (st[i] == tid);
        float r = 1.f;
        for (int q = 0; q < cnt; q++) r *= 0.99f;
        decay[tid] = r;
    }
    if (tid >= 64 && tid < 96) {
        int i = tid - 64;
        int after = 0;
        for (int j = i + 1; j < BS; j++) after += (st[j] == st[i]);
        float r = 0.01f;
        for (int q = 0; q < after; q++) r *= 0.99f;
        coeff[i] = r;
    }
    __syncthreads();

    for (int idx = tid; idx < TT*C; idx += NTH) {
        int t = idx >> 6, c = idx & 63;
        float v = decay[t] * ref_proj[idx];
        #pragma unroll 8
        for (int i = 0; i < BS; i++)
            if (st[i] == t) v += coeff[i] * refx[i*C + c];
        refnew[idx] = v;
        dout[2049 + idx] = v;
    }
    __syncthreads();

    for (int idx = tid; idx < BS*C; idx += NTH) {
        int bb = idx >> 6, c = idx & 63;
        float s = refx[idx];
        const float* twr = logit + bb*TT;
        #pragma unroll 16
        for (int t = 0; t < TT; t++) s += twr[t] * refnew[t*C + c];
        dout[idx] = s;
    }
    if (tid == 0) {
        float s = 0.f;
        for (int i = 0; i < BS; i++) s += lossv[i];
        dout[2048] = s * (1.f/(float)BS);
    }
}

// ---------------- launch ----------------
extern "C" void kernel_launch(void* const* d_in, const int* in_sizes, int n_in,
                              void* d_out, int out_size) {
    const float* x        = (const float*)d_in[0];
    const float* ref_x    = (const float*)d_in[1];
    const int*   ref_types= (const int*)  d_in[2];
    const float* conv1_w  = (const float*)d_in[3];
    const float* bn1_g    = (const float*)d_in[4];
    const float* bn1_b    = (const float*)d_in[5];
    const float* bn1_m    = (const float*)d_in[6];
    const float* bn1_v    = (const float*)d_in[7];
    const float* conv2_w  = (const float*)d_in[8];
    const float* bn2_g    = (const float*)d_in[9];
    const float* bn2_b    = (const float*)d_in[10];
    const float* bn2_m    = (const float*)d_in[11];
    const float* bn2_v    = (const float*)d_in[12];
    const float* mlp_w1   = (const float*)d_in[13];
    const float* mlp_b1   = (const float*)d_in[14];
    const float* mlp_w2   = (const float*)d_in[15];
    const float* mlp_b2   = (const float*)d_in[16];
    const float* ref_proj = (const float*)d_in[17];
    float* out = (float*)d_out;

    cudaFuncSetAttribute(conv_mma<1>, cudaFuncAttributeMaxDynamicSharedMemorySize, CONV_SMEM);
    cudaFuncSetAttribute(conv_mma<0>, cudaFuncAttributeMaxDynamicSharedMemorySize, CONV_SMEM);
    cudaFuncSetAttribute(tail_kernel, cudaFuncAttributeMaxDynamicSharedMemorySize, TAIL_SMEM_BYTES);

    xpose_kernel<<<dim3(HW/64, BS), 256>>>(x);
    prep_kernel<<<288, 256>>>(conv1_w, bn1_g, bn1_b, bn1_m, bn1_v,
                              conv2_w, bn2_g, bn2_b, bn2_m, bn2_v);

    dim3 cgrid(NTX, NTY, BS);
    conv_mma<1><<<cgrid, 256, CONV_SMEM>>>(0);
    conv_mma<0><<<cgrid, 256, CONV_SMEM>>>(0);

    tail_kernel<<<1, 1024, TAIL_SMEM_BYTES>>>(ref_x, ref_types, mlp_w1, mlp_b1,
                                              mlp_w2, mlp_b2, ref_proj, out);
}

// round 7
// speedup vs baseline: 3.6172x; 1.6274x over previous
#include <cuda_runtime.h>
#include <cuda_bf16.h>
#include <cstdint>

// ---------------- problem constants ----------------
#define BS   32
#define C    64
#define H    96
#define W    96
#define HW   (H*W)
#define CHW  ((size_t)C*HW)
#define TT   64
#define HID  128
#define EPS  1e-5f

// conv tiling: CTA = 4 rows x 32 cols = 128 px (M), 64 oc (N), K = 9*64
#define NTX 3
#define NTY 24
#define NT  (NTX*NTY)        // 72 tiles/image

// halo tile: 6 rows x 34 cols = 204 pixel-rows, each 64 bf16 = 128B
#define TPX 204
#define OFF_TH 0
#define OFF_B0 26624
#define OFF_B1 43008
#define CONV_SMEM 59392      // 3 CTAs/SM (174KB < 228KB)

#define TAILB_SMEM_FLOATS (2048+4096+2048+160)
#define TAILB_SMEM_BYTES  (TAILB_SMEM_FLOATS*4)

// ---------------- device scratch ----------------
__device__ uint32_t g_x [BS*HW*32];   // x, pixel-major bf16 (2 ic per u32)
__device__ uint32_t g_f1[BS*HW*32];   // conv1 out, same format
__device__ uint32_t g_wbm1[9*4096];   // weights: per slice 16KB = hi 8KB + lo 8KB, ldsm-swizzled
__device__ uint32_t g_wbm2[9*4096];
__device__ float    g_bias1[C];
__device__ float    g_bias2[C];
__device__ float    g_part[BS*NT*C];
__device__ float    g_logits[BS*TT];

// ---------------- helpers ----------------
static __device__ __forceinline__ uint32_t smem_u32(const void* p) {
    uint32_t a;
    asm("{ .reg .u64 t; cvta.to.shared.u64 t, %1; cvt.u32.u64 %0, t; }" : "=r"(a) : "l"(p));
    return a;
}
static __device__ __forceinline__ void ldsm4(uint32_t* r, uint32_t a) {
    asm volatile("ldmatrix.sync.aligned.m8n8.x4.shared.b16 {%0,%1,%2,%3}, [%4];"
        : "=r"(r[0]), "=r"(r[1]), "=r"(r[2]), "=r"(r[3]) : "r"(a));
}
static __device__ __forceinline__ void mma16816(float* c, const uint32_t* a, uint32_t b0, uint32_t b1) {
    asm volatile("mma.sync.aligned.m16n8k16.row.col.f32.bf16.bf16.f32 "
        "{%0,%1,%2,%3}, {%4,%5,%6,%7}, {%8,%9}, {%0,%1,%2,%3};"
        : "+f"(c[0]), "+f"(c[1]), "+f"(c[2]), "+f"(c[3])
        : "r"(a[0]), "r"(a[1]), "r"(a[2]), "r"(a[3]), "r"(b0), "r"(b1));
}
static __device__ __forceinline__ void cp16(uint32_t dst, const void* src) {
    asm volatile("cp.async.cg.shared.global [%0], [%1], 16;" :: "r"(dst), "l"(src));
}
static __device__ __forceinline__ void cp_commit() {
    asm volatile("cp.async.commit_group;" ::: "memory");
}
static __device__ __forceinline__ void cp_wait0() {
    asm volatile("cp.async.wait_group 0;" ::: "memory");
}

// ---------------- transpose x: [ic][py][px] fp32 -> [px][ic] bf16 ------
__global__ void xpose_kernel(const float* __restrict__ x) {
    __shared__ float st[64*65];
    const int tid = threadIdx.x;
    const int b = blockIdx.y;
    const int p0 = blockIdx.x * 64;
    const float* xb = x + (size_t)b * CHW;
    for (int i = tid; i < 64*64; i += 256) {
        int ic = i >> 6, p = i & 63;
        st[p*65 + ic] = xb[(size_t)ic*HW + p0 + p];
    }
    __syncthreads();
    for (int i = tid; i < 64*32; i += 256) {
        int p = i >> 5, pr = i & 31;
        __nv_bfloat162 v;
        v.x = __float2bfloat16(st[p*65 + 2*pr]);
        v.y = __float2bfloat16(st[p*65 + 2*pr + 1]);
        g_x[((size_t)(b*HW + p0 + p) << 5) + pr] = *(uint32_t*)&v;
    }
}

// ---------------- prep: fold BN, split hi/lo, ldsm-swizzle weights -----
__global__ void prep_kernel(const float* __restrict__ w1, const float* __restrict__ g1,
                            const float* __restrict__ b1, const float* __restrict__ m1,
                            const float* __restrict__ v1,
                            const float* __restrict__ w2, const float* __restrict__ g2,
                            const float* __restrict__ b2, const float* __restrict__ m2,
                            const float* __restrict__ v2) {
    int idx = blockIdx.x*256 + threadIdx.x;
    if (idx < 2*9*4096) {
        int cv = idx / 36864;
        int r  = idx - cv*36864;
        int s  = r >> 12;
        int q  = r & 4095;
        int oc = q >> 6;
        int ic = q & 63;
        const float* w = cv ? w2 : w1;
        const float* g = cv ? g2 : g1;
        const float* v = cv ? v2 : v1;
        float f = w[(oc*C + ic)*9 + s] * (g[oc] * rsqrtf(v[oc] + EPS));
        __nv_bfloat16 h = __float2bfloat16(f);
        float res = f - __bfloat162float(h);
        __nv_bfloat16 l = __float2bfloat16(res);
        uint32_t e = (uint32_t)oc*64 + ((uint32_t)ic ^ (((uint32_t)oc & 7u) << 3));
        __nv_bfloat16* dst = (__nv_bfloat16*)(cv ? g_wbm2 : g_wbm1) + (size_t)s*8192;
        dst[e]        = h;
        dst[4096 + e] = l;
    }
    if (idx < C) {
        g_bias1[idx] = b1[idx] - m1[idx]*g1[idx]*rsqrtf(v1[idx] + EPS);
        g_bias2[idx] = b2[idx] - m2[idx]*g2[idx]*rsqrtf(v2[idx] + EPS);
    }
}

// ---------------- HMMA conv: 2-term (Ah*Bh + Ah*Bl) implicit GEMM ------
// STORE=1: reads g_x, writes g_f1 (pixel-major bf16)
// STORE=0: reads g_f1, writes pooled partials -> g_part
template<int STORE>
__launch_bounds__(256, 3)
__global__ void conv_mma(int dummy) {
    extern __shared__ uint8_t sm[];
    const uint32_t sb = smem_u32(sm);

    const int tid  = threadIdx.x;
    const int lane = tid & 31;
    const int wrp  = tid >> 5;
    const int x0 = blockIdx.x * 32, y0 = blockIdx.y * 4;
    const int b  = blockIdx.z;

    const uint32_t* gin = STORE ? g_x : g_f1;
    const uint32_t* gwb = STORE ? g_wbm1 : g_wbm2;
    const float*   bias = STORE ? g_bias1 : g_bias2;

    // prefetch B slice 0 (16KB)
    {
        uint32_t dst = sb + OFF_B0;
        #pragma unroll
        for (int i = 0; i < 4; i++)
            cp16(dst + (tid + i*256)*16, gwb + (size_t)(tid + i*256)*4);
        cp_commit();
    }

    // fill halo tile (bf16, swizzled rows of 128B)
    const uint4* inb = (const uint4*)gin + ((size_t)b*HW << 3);
    for (int i = tid; i < TPX*8; i += 256) {
        int pxl = i >> 3, ch4 = i & 7;
        int rr = pxl / 34, cc = pxl - rr*34;
        int py = y0 + rr - 1, px = x0 + cc - 1;
        uint4 v = make_uint4(0,0,0,0);
        if (py >= 0 && py < H && px >= 0 && px < W)
            v = inb[((size_t)(py*W + px) << 3) + ch4];
        uint32_t boff = (uint32_t)pxl*128 + (((uint32_t)ch4*16) ^ (((uint32_t)pxl & 7u) << 4));
        *(uint4*)(sm + OFF_TH + boff) = v;
    }

    // per-lane ldsm address components
    const int g  = lane >> 3, lr = lane & 7;
    const int mb = (wrp & 3) * 32;
    const int nb = (wrp >> 2) * 32;
    const uint32_t kaddA = (g >= 2) ? 16u : 0u;
    const uint32_t kaddB = (uint32_t)(g & 1) << 4;
    int pA[2];
    uint32_t bAddr[2];
    #pragma unroll
    for (int f = 0; f < 2; f++) {
        int p = mb + f*16 + ((g & 1) << 3) + lr;
        pA[f] = (p >> 5)*34 + (p & 31);
        int oc = nb + f*16 + ((g >= 2) ? 8 : 0) + lr;
        bAddr[f] = (uint32_t)oc*128 + (kaddB ^ ((((uint32_t)oc & 7u) << 4)));
    }

    float acc[2][4][4];
    #pragma unroll
    for (int m = 0; m < 2; m++)
        #pragma unroll
        for (int n = 0; n < 4; n++)
            #pragma unroll
            for (int q = 0; q < 4; q++) acc[m][n][q] = 0.f;

    for (int s = 0; s < 9; s++) {
        cp_wait0();
        __syncthreads();
        if (s < 8) {
            uint32_t dst = sb + (((s+1) & 1) ? OFF_B1 : OFF_B0);
            const uint32_t* src = gwb + (size_t)(s+1)*4096;
            #pragma unroll
            for (int i = 0; i < 4; i++)
                cp16(dst + (tid + i*256)*16, src + (size_t)(tid + i*256)*4);
            cp_commit();
        }
        const int ky = s / 3, kx = s - 3*(s/3);
        const int soff = ky*34 + kx;
        const uint32_t bbuf = sb + ((s & 1) ? OFF_B1 : OFF_B0);

        #pragma unroll
        for (int kc = 0; kc < 4; kc++) {
            uint32_t AH[2][4];
            #pragma unroll
            for (int f = 0; f < 2; f++) {
                uint32_t pxl = (uint32_t)(pA[f] + soff);
                uint32_t aoff = pxl*128 + (((uint32_t)kc*32 + kaddA) ^ ((pxl & 7u) << 4));
                ldsm4(AH[f], sb + OFF_TH + aoff);
            }
            #pragma unroll
            for (int f = 0; f < 2; f++) {
                uint32_t r[4];
                ldsm4(r, bbuf + (bAddr[f] ^ ((uint32_t)kc*32)));
                mma16816(acc[0][2*f],   AH[0], r[0], r[1]);
                mma16816(acc[0][2*f+1], AH[0], r[2], r[3]);
                mma16816(acc[1][2*f],   AH[1], r[0], r[1]);
                mma16816(acc[1][2*f+1], AH[1], r[2], r[3]);
                ldsm4(r, bbuf + 8192 + (bAddr[f] ^ ((uint32_t)kc*32)));
                mma16816(acc[0][2*f],   AH[0], r[0], r[1]);
                mma16816(acc[0][2*f+1], AH[0], r[2], r[3]);
                mma16816(acc[1][2*f],   AH[1], r[0], r[1]);
                mma16816(acc[1][2*f+1], AH[1], r[2], r[3]);
            }
        }
    }

    // ---------------- epilogue ----------------
    if (STORE) {
        uint32_t* f1b = g_f1 + ((size_t)b*HW << 5);
        #pragma unroll
        for (int m = 0; m < 2; m++) {
            #pragma unroll
            for (int n = 0; n < 4; n++) {
                int oc = nb + n*8 + (lane & 3)*2;
                float b0 = bias[oc], b1v = bias[oc+1];
                #pragma unroll
                for (int hh = 0; hh < 2; hh++) {
                    int p = mb + m*16 + (lane >> 2) + hh*8;
                    int py = y0 + (p >> 5), px = x0 + (p & 31);
                    __nv_bfloat162 v;
                    v.x = __float2bfloat16(fmaxf(acc[m][n][hh*2]   + b0,  0.f));
                    v.y = __float2bfloat16(fmaxf(acc[m][n][hh*2+1] + b1v, 0.f));
                    f1b[((size_t)(py*W + px) << 5) + (oc >> 1)] = *(uint32_t*)&v;
                }
            }
        }
    } else {
        float cs[4][2];
        #pragma unroll
        for (int n = 0; n < 4; n++) {
            int oc = nb + n*8 + (lane & 3)*2;
            float b0 = bias[oc], b1v = bias[oc+1];
            float s0 = 0.f, s1 = 0.f;
            #pragma unroll
            for (int m = 0; m < 2; m++) {
                s0 += fmaxf(acc[m][n][0] + b0, 0.f) + fmaxf(acc[m][n][2] + b0, 0.f);
                s1 += fmaxf(acc[m][n][1] + b1v, 0.f) + fmaxf(acc[m][n][3] + b1v, 0.f);
            }
            #pragma unroll
            for (int d = 4; d < 32; d <<= 1) {
                s0 += __shfl_xor_sync(0xffffffffu, s0, d);
                s1 += __shfl_xor_sync(0xffffffffu, s1, d);
            }
            cs[n][0] = s0; cs[n][1] = s1;
        }
        __syncthreads();                       // tile reads done -> reuse as pool
        float* pool = (float*)(sm + OFF_TH);   // [4 mrow][64 oc]
        if (lane < 4) {
            #pragma unroll
            for (int n = 0; n < 4; n++) {
                int oc = nb + n*8 + lane*2;
                pool[(wrp & 3)*64 + oc]     = cs[n][0];
                pool[(wrp & 3)*64 + oc + 1] = cs[n][1];
            }
        }
        __syncthreads();
        if (tid < C) {
            float s = pool[tid] + pool[64 + tid] + pool[128 + tid] + pool[192 + tid];
            int tileIdx = blockIdx.y * NTX + blockIdx.x;
            g_part[((size_t)b*NT + tileIdx)*C + tid] = s;
        }
    }
}

// ---------------- tailA: per-sample pool finish + MLP -> logits --------
__launch_bounds__(128)
__global__ void tailA_kernel(const float* __restrict__ w1, const float* __restrict__ b1,
                             const float* __restrict__ w2, const float* __restrict__ b2) {
    __shared__ float red[128];
    __shared__ float feat[64];
    __shared__ float hidden[128];
    const int tid = threadIdx.x;
    const int b = blockIdx.x;

    // pool reduce: 2 halves of 36 tiles each
    {
        int half = tid >> 6, c = tid & 63;
        float s = 0.f;
        const float* gp = g_part + ((size_t)b*NT + half*36)*C + c;
        #pragma unroll 9
        for (int t = 0; t < 36; t++) s += gp[t*C];
        red[tid] = s;
    }
    __syncthreads();
    if (tid < 64) feat[tid] = (red[tid] + red[tid + 64]) * (1.f/(float)HW);
    __syncthreads();

    // hidden = relu(feat @ w1 + b1)
    {
        float h = b1[tid];
        #pragma unroll 16
        for (int i = 0; i < C; i++) h += feat[i] * w1[i*HID + tid];
        hidden[tid] = fmaxf(h, 0.f);
    }
    __syncthreads();

    // logits = hidden @ w2 + b2
    if (tid < TT) {
        float s = b2[tid];
        #pragma unroll 16
        for (int j = 0; j < HID; j++) s += hidden[j] * w2[j*TT + tid];
        g_logits[b*TT + tid] = s;
    }
}

// ---------------- tailB: softmax, loss, EMA, outputs -------------------
__launch_bounds__(1024)
__global__ void tailB_kernel(const float* __restrict__ ref_x, const int* __restrict__ ref_types,
                             const float* __restrict__ ref_proj, float* __restrict__ dout) {
    extern __shared__ float smf[];
    float* logit  = smf;             // [32][64] -> becomes type_weights
    float* refnew = logit + 2048;    // [64][64]
    float* refx   = refnew + 4096;   // [32][64]
    float* lossv  = refx + 2048;     // [32]
    float* coeff  = lossv + 32;      // [32]
    float* decay  = coeff + 32;      // [64]
    int*   st     = (int*)(decay + 64);

    const int tid = threadIdx.x;
    const int NTH = 1024;
    if (tid < BS) st[tid] = ref_types[tid];
    for (int i = tid; i < BS*TT; i += NTH) logit[i] = g_logits[i];
    for (int i = tid; i < BS*C; i += NTH) refx[i] = ref_x[i];
    __syncthreads();

    {
        const int wp = tid >> 5, ln = tid & 31;
        float* lr = logit + wp*TT;
        float a = lr[ln], c2 = lr[ln + 32];
        float tgt = lr[st[wp]];
        float mx = fmaxf(a, c2);
        #pragma unroll
        for (int s = 16; s; s >>= 1) mx = fmaxf(mx, __shfl_xor_sync(0xffffffffu, mx, s));
        float ea = expf(a - mx), eb = expf(c2 - mx);
        float sum = ea + eb;
        #pragma unroll
        for (int s = 16; s; s >>= 1) sum += __shfl_xor_sync(0xffffffffu, sum, s);
        if (ln == 0) lossv[wp] = mx + logf(sum) - tgt;
        float inv = 1.f / sum;
        __syncwarp();
        lr[ln]      = ea * inv;
        lr[ln + 32] = eb * inv;
    }
    if (tid < TT) {
        int cnt = 0;
        for (int i = 0; i < BS; i++) cnt += (st[i] == tid);
        float r = 1.f;
        for (int q = 0; q < cnt; q++) r *= 0.99f;
        decay[tid] = r;
    }
    if (tid >= 64 && tid < 96) {
        int i = tid - 64;
        int after = 0;
        for (int j = i + 1; j < BS; j++) after += (st[j] == st[i]);
        float r = 0.01f;
        for (int q = 0; q < after; q++) r *= 0.99f;
        coeff[i] = r;
    }
    __syncthreads();

    for (int idx = tid; idx < TT*C; idx += NTH) {
        int t = idx >> 6, c = idx & 63;
        float v = decay[t] * ref_proj[idx];
        #pragma unroll 8
        for (int i = 0; i < BS; i++)
            if (st[i] == t) v += coeff[i] * refx[i*C + c];
        refnew[idx] = v;
        dout[2049 + idx] = v;
    }
    __syncthreads();

    for (int idx = tid; idx < BS*C; idx += NTH) {
        int bb = idx >> 6, c = idx & 63;
        float s = refx[idx];
        const float* twr = logit + bb*TT;
        #pragma unroll 16
        for (int t = 0; t < TT; t++) s += twr[t] * refnew[t*C + c];
        dout[idx] = s;
    }
    if (tid == 0) {
        float s = 0.f;
        for (int i = 0; i < BS; i++) s += lossv[i];
        dout[2048] = s * (1.f/(float)BS);
    }
}

// ---------------- launch ----------------
extern "C" void kernel_launch(void* const* d_in, const int* in_sizes, int n_in,
                              void* d_out, int out_size) {
    const float* x        = (const float*)d_in[0];
    const float* ref_x    = (const float*)d_in[1];
    const int*   ref_types= (const int*)  d_in[2];
    const float* conv1_w  = (const float*)d_in[3];
    const float* bn1_g    = (const float*)d_in[4];
    const float* bn1_b    = (const float*)d_in[5];
    const float* bn1_m    = (const float*)d_in[6];
    const float* bn1_v    = (const float*)d_in[7];
    const float* conv2_w  = (const float*)d_in[8];
    const float* bn2_g    = (const float*)d_in[9];
    const float* bn2_b    = (const float*)d_in[10];
    const float* bn2_m    = (const float*)d_in[11];
    const float* bn2_v    = (const float*)d_in[12];
    const float* mlp_w1   = (const float*)d_in[13];
    const float* mlp_b1   = (const float*)d_in[14];
    const float* mlp_w2   = (const float*)d_in[15];
    const float* mlp_b2   = (const float*)d_in[16];
    const float* ref_proj = (const float*)d_in[17];
    float* out = (float*)d_out;

    cudaFuncSetAttribute(conv_mma<1>, cudaFuncAttributeMaxDynamicSharedMemorySize, CONV_SMEM);
    cudaFuncSetAttribute(conv_mma<0>, cudaFuncAttributeMaxDynamicSharedMemorySize, CONV_SMEM);
    cudaFuncSetAttribute(tailB_kernel, cudaFuncAttributeMaxDynamicSharedMemorySize, TAILB_SMEM_BYTES);

    xpose_kernel<<<dim3(HW/64, BS), 256>>>(x);
    prep_kernel<<<288, 256>>>(conv1_w, bn1_g, bn1_b, bn1_m, bn1_v,
                              conv2_w, bn2_g, bn2_b, bn2_m, bn2_v);

    dim3 cgrid(NTX, NTY, BS);
    conv_mma<1><<<cgrid, 256, CONV_SMEM>>>(0);
    conv_mma<0><<<cgrid, 256, CONV_SMEM>>>(0);

    tailA_kernel<<<BS, 128>>>(mlp_w1, mlp_b1, mlp_w2, mlp_b2);
    tailB_kernel<<<1, 1024, TAILB_SMEM_BYTES>>>(ref_x, ref_types, ref_proj, out);
}

// round 8
// speedup vs baseline: 4.8745x; 1.3476x over previous
#include <cuda_runtime.h>
#include <cuda_bf16.h>
#include <cstdint>

// ---------------- problem constants ----------------
#define BS   32
#define C    64
#define H    96
#define W    96
#define HW   (H*W)
#define CHW  ((size_t)C*HW)
#define TT   64
#define HID  128
#define EPS  1e-5f

// conv tiling: CTA = 4 rows x 32 cols = 128 px (M), 64 oc (N), K = 9*64
#define NTX 3
#define NTY 24
#define NT  (NTX*NTY)        // 72 tiles/image

// halo tile: 6 rows x 34 cols = 204 pixel-rows, each 64 bf16 = 128B
#define TPX 204
#define OFF_TH 0
#define OFF_B0 26624
#define OFF_B1 34816
#define CONV_SMEM 43008      // 4 CTAs/SM (172KB < 228KB)

#define TAILB_SMEM_FLOATS (2048+4096+2048+160)
#define TAILB_SMEM_BYTES  (TAILB_SMEM_FLOATS*4)

// ---------------- device scratch ----------------
__device__ uint32_t g_x [BS*HW*32];   // x, pixel-major bf16 (2 ic per u32)
__device__ uint32_t g_f1[BS*HW*32];   // conv1 out, same format
__device__ uint32_t g_wbm1[9*2048];   // weights: per slice 8KB bf16 hi, ldsm-swizzled
__device__ uint32_t g_wbm2[9*2048];
__device__ float    g_bias1[C];
__device__ float    g_bias2[C];
__device__ float    g_part[BS*NT*C];
__device__ float    g_logits[BS*TT];

// ---------------- helpers ----------------
static __device__ __forceinline__ uint32_t smem_u32(const void* p) {
    uint32_t a;
    asm("{ .reg .u64 t; cvta.to.shared.u64 t, %1; cvt.u32.u64 %0, t; }" : "=r"(a) : "l"(p));
    return a;
}
static __device__ __forceinline__ void ldsm4(uint32_t* r, uint32_t a) {
    asm volatile("ldmatrix.sync.aligned.m8n8.x4.shared.b16 {%0,%1,%2,%3}, [%4];"
        : "=r"(r[0]), "=r"(r[1]), "=r"(r[2]), "=r"(r[3]) : "r"(a));
}
static __device__ __forceinline__ void mma16816(float* c, const uint32_t* a, uint32_t b0, uint32_t b1) {
    asm volatile("mma.sync.aligned.m16n8k16.row.col.f32.bf16.bf16.f32 "
        "{%0,%1,%2,%3}, {%4,%5,%6,%7}, {%8,%9}, {%0,%1,%2,%3};"
        : "+f"(c[0]), "+f"(c[1]), "+f"(c[2]), "+f"(c[3])
        : "r"(a[0]), "r"(a[1]), "r"(a[2]), "r"(a[3]), "r"(b0), "r"(b1));
}
static __device__ __forceinline__ void cp16(uint32_t dst, const void* src) {
    asm volatile("cp.async.cg.shared.global [%0], [%1], 16;" :: "r"(dst), "l"(src));
}
static __device__ __forceinline__ void cp_commit() {
    asm volatile("cp.async.commit_group;" ::: "memory");
}
static __device__ __forceinline__ void cp_wait0() {
    asm volatile("cp.async.wait_group 0;" ::: "memory");
}

// ---------------- transpose x: [ic][py][px] fp32 -> [px][ic] bf16 ------
__global__ void xpose_kernel(const float* __restrict__ x) {
    __shared__ float st[64*65];
    const int tid = threadIdx.x;
    const int b = blockIdx.y;
    const int p0 = blockIdx.x * 64;
    const float* xb = x + (size_t)b * CHW;
    for (int i = tid; i < 64*64; i += 256) {
        int ic = i >> 6, p = i & 63;
        st[p*65 + ic] = xb[(size_t)ic*HW + p0 + p];
    }
    __syncthreads();
    for (int i = tid; i < 64*32; i += 256) {
        int p = i >> 5, pr = i & 31;
        __nv_bfloat162 v;
        v.x = __float2bfloat16(st[p*65 + 2*pr]);
        v.y = __float2bfloat16(st[p*65 + 2*pr + 1]);
        g_x[((size_t)(b*HW + p0 + p) << 5) + pr] = *(uint32_t*)&v;
    }
}

// ---------------- prep: fold BN, bf16, ldsm-swizzle weights ------------
__global__ void prep_kernel(const float* __restrict__ w1, const float* __restrict__ g1,
                            const float* __restrict__ b1, const float* __restrict__ m1,
                            const float* __restrict__ v1,
                            const float* __restrict__ w2, const float* __restrict__ g2,
                            const float* __restrict__ b2, const float* __restrict__ m2,
                            const float* __restrict__ v2) {
    int idx = blockIdx.x*256 + threadIdx.x;
    if (idx < 2*9*4096) {
        int cv = idx / 36864;
        int r  = idx - cv*36864;
        int s  = r >> 12;
        int q  = r & 4095;
        int oc = q >> 6;
        int ic = q & 63;
        const float* w = cv ? w2 : w1;
        const float* g = cv ? g2 : g1;
        const float* v = cv ? v2 : v1;
        float f = w[(oc*C + ic)*9 + s] * (g[oc] * rsqrtf(v[oc] + EPS));
        uint32_t e = (uint32_t)oc*64 + ((uint32_t)ic ^ (((uint32_t)oc & 7u) << 3));
        __nv_bfloat16* dst = (__nv_bfloat16*)(cv ? g_wbm2 : g_wbm1) + (size_t)s*4096;
        dst[e] = __float2bfloat16(f);
    }
    if (idx < C) {
        g_bias1[idx] = b1[idx] - m1[idx]*g1[idx]*rsqrtf(v1[idx] + EPS);
        g_bias2[idx] = b2[idx] - m2[idx]*g2[idx]*rsqrtf(v2[idx] + EPS);
    }
}

// ---------------- HMMA conv: bf16 implicit GEMM ------------------------
// STORE=1: reads g_x, writes g_f1 (pixel-major bf16)
// STORE=0: reads g_f1, writes pooled partials -> g_part
template<int STORE>
__launch_bounds__(256, 4)
__global__ void conv_mma(int dummy) {
    extern __shared__ uint8_t sm[];
    const uint32_t sb = smem_u32(sm);

    const int tid  = threadIdx.x;
    const int lane = tid & 31;
    const int wrp  = tid >> 5;
    const int x0 = blockIdx.x * 32, y0 = blockIdx.y * 4;
    const int b  = blockIdx.z;

    const uint32_t* gin = STORE ? g_x : g_f1;
    const uint32_t* gwb = STORE ? g_wbm1 : g_wbm2;
    const float*   bias = STORE ? g_bias1 : g_bias2;

    // prefetch B slice 0 (8KB)
    {
        uint32_t dst = sb + OFF_B0;
        #pragma unroll
        for (int i = 0; i < 2; i++)
            cp16(dst + (tid + i*256)*16, gwb + (size_t)(tid + i*256)*4);
        cp_commit();
    }

    // fill halo tile (bf16, swizzled rows of 128B)
    const uint4* inb = (const uint4*)gin + ((size_t)b*HW << 3);
    for (int i = tid; i < TPX*8; i += 256) {
        int pxl = i >> 3, ch4 = i & 7;
        int rr = pxl / 34, cc = pxl - rr*34;
        int py = y0 + rr - 1, px = x0 + cc - 1;
        uint4 v = make_uint4(0,0,0,0);
        if (py >= 0 && py < H && px >= 0 && px < W)
            v = inb[((size_t)(py*W + px) << 3) + ch4];
        uint32_t boff = (uint32_t)pxl*128 + (((uint32_t)ch4*16) ^ (((uint32_t)pxl & 7u) << 4));
        *(uint4*)(sm + OFF_TH + boff) = v;
    }

    // per-lane ldsm address components
    const int g  = lane >> 3, lr = lane & 7;
    const int mb = (wrp & 3) * 32;
    const int nb = (wrp >> 2) * 32;
    const uint32_t kaddA = (g >= 2) ? 16u : 0u;
    const uint32_t kaddB = (uint32_t)(g & 1) << 4;
    int pA[2];
    uint32_t bAddr[2];
    #pragma unroll
    for (int f = 0; f < 2; f++) {
        int p = mb + f*16 + ((g & 1) << 3) + lr;
        pA[f] = (p >> 5)*34 + (p & 31);
        int oc = nb + f*16 + ((g >= 2) ? 8 : 0) + lr;
        bAddr[f] = (uint32_t)oc*128 + (kaddB ^ ((((uint32_t)oc & 7u) << 4)));
    }

    float acc[2][4][4];
    #pragma unroll
    for (int m = 0; m < 2; m++)
        #pragma unroll
        for (int n = 0; n < 4; n++)
            #pragma unroll
            for (int q = 0; q < 4; q++) acc[m][n][q] = 0.f;

    for (int s = 0; s < 9; s++) {
        cp_wait0();
        __syncthreads();
        if (s < 8) {
            uint32_t dst = sb + (((s+1) & 1) ? OFF_B1 : OFF_B0);
            const uint32_t* src = gwb + (size_t)(s+1)*2048;
            #pragma unroll
            for (int i = 0; i < 2; i++)
                cp16(dst + (tid + i*256)*16, src + (size_t)(tid + i*256)*4);
            cp_commit();
        }
        const int ky = s / 3, kx = s - 3*(s/3);
        const int soff = ky*34 + kx;
        const uint32_t bbuf = sb + ((s & 1) ? OFF_B1 : OFF_B0);

        #pragma unroll
        for (int kc = 0; kc < 4; kc++) {
            uint32_t AH[2][4];
            #pragma unroll
            for (int f = 0; f < 2; f++) {
                uint32_t pxl = (uint32_t)(pA[f] + soff);
                uint32_t aoff = pxl*128 + (((uint32_t)kc*32 + kaddA) ^ ((pxl & 7u) << 4));
                ldsm4(AH[f], sb + OFF_TH + aoff);
            }
            #pragma unroll
            for (int f = 0; f < 2; f++) {
                uint32_t r[4];
                ldsm4(r, bbuf + (bAddr[f] ^ ((uint32_t)kc*32)));
                mma16816(acc[0][2*f],   AH[0], r[0], r[1]);
                mma16816(acc[0][2*f+1], AH[0], r[2], r[3]);
                mma16816(acc[1][2*f],   AH[1], r[0], r[1]);
                mma16816(acc[1][2*f+1], AH[1], r[2], r[3]);
            }
        }
    }

    // ---------------- epilogue ----------------
    if (STORE) {
        uint32_t* f1b = g_f1 + ((size_t)b*HW << 5);
        #pragma unroll
        for (int m = 0; m < 2; m++) {
            #pragma unroll
            for (int n = 0; n < 4; n++) {
                int oc = nb + n*8 + (lane & 3)*2;
                float b0 = bias[oc], b1v = bias[oc+1];
                #pragma unroll
                for (int hh = 0; hh < 2; hh++) {
                    int p = mb + m*16 + (lane >> 2) + hh*8;
                    int py = y0 + (p >> 5), px = x0 + (p & 31);
                    __nv_bfloat162 v;
                    v.x = __float2bfloat16(fmaxf(acc[m][n][hh*2]   + b0,  0.f));
                    v.y = __float2bfloat16(fmaxf(acc[m][n][hh*2+1] + b1v, 0.f));
                    f1b[((size_t)(py*W + px) << 5) + (oc >> 1)] = *(uint32_t*)&v;
                }
            }
        }
    } else {
        float cs[4][2];
        #pragma unroll
        for (int n = 0; n < 4; n++) {
            int oc = nb + n*8 + (lane & 3)*2;
            float b0 = bias[oc], b1v = bias[oc+1];
            float s0 = 0.f, s1 = 0.f;
            #pragma unroll
            for (int m = 0; m < 2; m++) {
                s0 += fmaxf(acc[m][n][0] + b0, 0.f) + fmaxf(acc[m][n][2] + b0, 0.f);
                s1 += fmaxf(acc[m][n][1] + b1v, 0.f) + fmaxf(acc[m][n][3] + b1v, 0.f);
            }
            #pragma unroll
            for (int d = 4; d < 32; d <<= 1) {
                s0 += __shfl_xor_sync(0xffffffffu, s0, d);
                s1 += __shfl_xor_sync(0xffffffffu, s1, d);
            }
            cs[n][0] = s0; cs[n][1] = s1;
        }
        __syncthreads();                       // tile reads done -> reuse as pool
        float* pool = (float*)(sm + OFF_TH);   // [4 mrow][64 oc]
        if (lane < 4) {
            #pragma unroll
            for (int n = 0; n < 4; n++) {
                int oc = nb + n*8 + lane*2;
                pool[(wrp & 3)*64 + oc]     = cs[n][0];
                pool[(wrp & 3)*64 + oc + 1] = cs[n][1];
            }
        }
        __syncthreads();
        if (tid < C) {
            float s = pool[tid] + pool[64 + tid] + pool[128 + tid] + pool[192 + tid];
            int tileIdx = blockIdx.y * NTX + blockIdx.x;
            g_part[((size_t)b*NT + tileIdx)*C + tid] = s;
        }
    }
}

// ---------------- tailA: per-sample pool finish + MLP -> logits --------
__launch_bounds__(128)
__global__ void tailA_kernel(const float* __restrict__ w1, const float* __restrict__ b1,
                             const float* __restrict__ w2, const float* __restrict__ b2) {
    __shared__ float red[128];
    __shared__ float feat[64];
    __shared__ float hidden[128];
    const int tid = threadIdx.x;
    const int b = blockIdx.x;

    {
        int half = tid >> 6, c = tid & 63;
        float s = 0.f;
        const float* gp = g_part + ((size_t)b*NT + half*36)*C + c;
        #pragma unroll 9
        for (int t = 0; t < 36; t++) s += gp[t*C];
        red[tid] = s;
    }
    __syncthreads();
    if (tid < 64) feat[tid] = (red[tid] + red[tid + 64]) * (1.f/(float)HW);
    __syncthreads();

    {
        float h = b1[tid];
        #pragma unroll 16
        for (int i = 0; i < C; i++) h += feat[i] * w1[i*HID + tid];
        hidden[tid] = fmaxf(h, 0.f);
    }
    __syncthreads();

    if (tid < TT) {
        float s = b2[tid];
        #pragma unroll 16
        for (int j = 0; j < HID; j++) s += hidden[j] * w2[j*TT + tid];
        g_logits[b*TT + tid] = s;
    }
}

// ---------------- tailB: softmax, loss, EMA, outputs -------------------
__launch_bounds__(1024)
__global__ void tailB_kernel(const float* __restrict__ ref_x, const int* __restrict__ ref_types,
                             const float* __restrict__ ref_proj, float* __restrict__ dout) {
    extern __shared__ float smf[];
    float* logit  = smf;             // [32][64] -> becomes type_weights
    float* refnew = logit + 2048;    // [64][64]
    float* refx   = refnew + 4096;   // [32][64]
    float* lossv  = refx + 2048;     // [32]
    float* coeff  = lossv + 32;      // [32]
    float* decay  = coeff + 32;      // [64]
    int*   st     = (int*)(decay + 64);

    const int tid = threadIdx.x;
    const int NTH = 1024;
    if (tid < BS) st[tid] = ref_types[tid];
    for (int i = tid; i < BS*TT; i += NTH) logit[i] = g_logits[i];
    for (int i = tid; i < BS*C; i += NTH) refx[i] = ref_x[i];
    __syncthreads();

    {
        const int wp = tid >> 5, ln = tid & 31;
        float* lr = logit + wp*TT;
        float a = lr[ln], c2 = lr[ln + 32];
        float tgt = lr[st[wp]];
        float mx = fmaxf(a, c2);
        #pragma unroll
        for (int s = 16; s; s >>= 1) mx = fmaxf(mx, __shfl_xor_sync(0xffffffffu, mx, s));
        float ea = expf(a - mx), eb = expf(c2 - mx);
        float sum = ea + eb;
        #pragma unroll
        for (int s = 16; s; s >>= 1) sum += __shfl_xor_sync(0xffffffffu, sum, s);
        if (ln == 0) lossv[wp] = mx + logf(sum) - tgt;
        float inv = 1.f / sum;
        __syncwarp();
        lr[ln]      = ea * inv;
        lr[ln + 32] = eb * inv;
    }
    if (tid < TT) {
        int cnt = 0;
        for (int i = 0; i < BS; i++) cnt += (st[i] == tid);
        float r = 1.f;
        for (int q = 0; q < cnt; q++) r *= 0.99f;
        decay[tid] = r;
    }
    if (tid >= 64 && tid < 96) {
        int i = tid - 64;
        int after = 0;
        for (int j = i + 1; j < BS; j++) after += (st[j] == st[i]);
        float r = 0.01f;
        for (int q = 0; q < after; q++) r *= 0.99f;
        coeff[i] = r;
    }
    __syncthreads();

    for (int idx = tid; idx < TT*C; idx += NTH) {
        int t = idx >> 6, c = idx & 63;
        float v = decay[t] * ref_proj[idx];
        #pragma unroll 8
        for (int i = 0; i < BS; i++)
            if (st[i] == t) v += coeff[i] * refx[i*C + c];
        refnew[idx] = v;
        dout[2049 + idx] = v;
    }
    __syncthreads();

    for (int idx = tid; idx < BS*C; idx += NTH) {
        int bb = idx >> 6, c = idx & 63;
        float s = refx[idx];
        const float* twr = logit + bb*TT;
        #pragma unroll 16
        for (int t = 0; t < TT; t++) s += twr[t] * refnew[t*C + c];
        dout[idx] = s;
    }
    if (tid == 0) {
        float s = 0.f;
        for (int i = 0; i < BS; i++) s += lossv[i];
        dout[2048] = s * (1.f/(float)BS);
    }
}

// ---------------- launch ----------------
extern "C" void kernel_launch(void* const* d_in, const int* in_sizes, int n_in,
                              void* d_out, int out_size) {
    const float* x        = (const float*)d_in[0];
    const float* ref_x    = (const float*)d_in[1];
    const int*   ref_types= (const int*)  d_in[2];
    const float* conv1_w  = (const float*)d_in[3];
    const float* bn1_g    = (const float*)d_in[4];
    const float* bn1_b    = (const float*)d_in[5];
    const float* bn1_m    = (const float*)d_in[6];
    const float* bn1_v    = (const float*)d_in[7];
    const float* conv2_w  = (const float*)d_in[8];
    const float* bn2_g    = (const float*)d_in[9];
    const float* bn2_b    = (const float*)d_in[10];
    const float* bn2_m    = (const float*)d_in[11];
    const float* bn2_v    = (const float*)d_in[12];
    const float* mlp_w1   = (const float*)d_in[13];
    const float* mlp_b1   = (const float*)d_in[14];
    const float* mlp_w2   = (const float*)d_in[15];
    const float* mlp_b2   = (const float*)d_in[16];
    const float* ref_proj = (const float*)d_in[17];
    float* out = (float*)d_out;

    cudaFuncSetAttribute(conv_mma<1>, cudaFuncAttributeMaxDynamicSharedMemorySize, CONV_SMEM);
    cudaFuncSetAttribute(conv_mma<0>, cudaFuncAttributeMaxDynamicSharedMemorySize, CONV_SMEM);
    cudaFuncSetAttribute(tailB_kernel, cudaFuncAttributeMaxDynamicSharedMemorySize, TAILB_SMEM_BYTES);

    xpose_kernel<<<dim3(HW/64, BS), 256>>>(x);
    prep_kernel<<<288, 256>>>(conv1_w, bn1_g, bn1_b, bn1_m, bn1_v,
                              conv2_w, bn2_g, bn2_b, bn2_m, bn2_v);

    dim3 cgrid(NTX, NTY, BS);
    conv_mma<1><<<cgrid, 256, CONV_SMEM>>>(0);
    conv_mma<0><<<cgrid, 256, CONV_SMEM>>>(0);

    tailA_kernel<<<BS, 128>>>(mlp_w1, mlp_b1, mlp_w2, mlp_b2);
    tailB_kernel<<<1, 1024, TAILB_SMEM_BYTES>>>(ref_x, ref_types, ref_proj, out);
}